// round 3
// baseline (speedup 1.0000x reference)
#include <cuda_runtime.h>
#include <math.h>
#include <stdint.h>

#define B_ 2
#define S_ 2048
#define DM_ 1024
#define TD_ 1024
#define H_ 16
#define HD_ 64

// ---------------- scratch (static __device__: no allocation) ----------------
__device__ float g_qkv[(size_t)B_ * S_ * 3 * TD_];       // [B*S, 3072]
__device__ float g_q[(size_t)B_ * H_ * S_ * HD_];        // [B,H,S,HD]
__device__ float g_k[(size_t)B_ * H_ * S_ * HD_];
__device__ float g_v[(size_t)B_ * H_ * S_ * HD_];
__device__ float g_attn[(size_t)B_ * S_ * TD_];          // [B*S, 1024]
__device__ int   g_len[B_];

// ---------------- lengths from padding mask (dtype-sniffing) ----------------
__global__ void lengths_kernel(const unsigned char* __restrict__ mask) {
    int tid = threadIdx.x;
    if (tid < B_) g_len[tid] = 0;
    __syncthreads();
    // mask[0][0] is always true (lengths >= S/2). Detect storage dtype:
    // u8/bool: bytes 0,1 both 1.  f32 1.0: bytes 2,3 = 0x80,0x3f.
    // i32: byte4 == 1.  i64: byte4 == 0.
    int mode;
    if (mask[1] != 0) mode = 0;                                  // 1-byte bool
    else if (mask[2] == 0x80 && mask[3] == 0x3f) mode = 3;       // float32
    else if (mask[4] != 0) mode = 1;                             // int32
    else mode = 2;                                               // int64
    int c0 = 0, c1 = 0;
    for (int i = tid; i < B_ * S_; i += blockDim.x) {
        bool v;
        switch (mode) {
            case 0:  v = mask[i] != 0; break;
            case 1:  v = ((const int*)mask)[i] != 0; break;
            case 2:  v = ((const long long*)mask)[i] != 0LL; break;
            default: v = ((const float*)mask)[i] != 0.0f; break;
        }
        if (i < S_) c0 += v ? 1 : 0; else c1 += v ? 1 : 0;
    }
    if (c0) atomicAdd(&g_len[0], c0);
    if (c1) atomicAdd(&g_len[1], c1);
}

// ---------------- NT SGEMM: C[M,N] = A[M,K] * B[N,K]^T ----------------
// 128x128 block tile, K-step 8, 256 threads, 8x8 micro (4+4 split).
__global__ void __launch_bounds__(256) gemm_nt(const float* __restrict__ A,
                                               const float* __restrict__ Bm,
                                               float* __restrict__ C,
                                               int M, int N, int K) {
    __shared__ float As[8][128];
    __shared__ float Bs[8][128];
    const int tid  = threadIdx.x;
    const int warp = tid >> 5, lane = tid & 31;
    const int wm = warp & 3, wn = warp >> 2;      // warp grid 4(m) x 2(n)
    const int lm = lane >> 3, ln = lane & 7;      // lane grid 4(m) x 8(n)
    const int row0 = wm * 32 + lm * 4;            // +{0..3}, +16
    const int col0 = wn * 64 + ln * 4;            // +{0..3}, +32
    const int m0 = blockIdx.y * 128, n0 = blockIdx.x * 128;
    const int ldrow = tid >> 1, ldk = (tid & 1) * 4;
    const float* Ap = A  + (size_t)(m0 + ldrow) * K + ldk;
    const float* Bp = Bm + (size_t)(n0 + ldrow) * K + ldk;

    float acc[8][8];
#pragma unroll
    for (int i = 0; i < 8; i++)
#pragma unroll
        for (int j = 0; j < 8; j++) acc[i][j] = 0.f;

    float4 apre = *(const float4*)Ap;
    float4 bpre = *(const float4*)Bp;
    const int nk = K >> 3;
    for (int kt = 0; kt < nk; kt++) {
        As[ldk + 0][ldrow] = apre.x; As[ldk + 1][ldrow] = apre.y;
        As[ldk + 2][ldrow] = apre.z; As[ldk + 3][ldrow] = apre.w;
        Bs[ldk + 0][ldrow] = bpre.x; Bs[ldk + 1][ldrow] = bpre.y;
        Bs[ldk + 2][ldrow] = bpre.z; Bs[ldk + 3][ldrow] = bpre.w;
        __syncthreads();
        if (kt + 1 < nk) {
            apre = *(const float4*)(Ap + (size_t)(kt + 1) * 8);
            bpre = *(const float4*)(Bp + (size_t)(kt + 1) * 8);
        }
#pragma unroll
        for (int kk = 0; kk < 8; kk++) {
            float a[8], b[8];
            *(float4*)&a[0] = *(const float4*)&As[kk][row0];
            *(float4*)&a[4] = *(const float4*)&As[kk][row0 + 16];
            *(float4*)&b[0] = *(const float4*)&Bs[kk][col0];
            *(float4*)&b[4] = *(const float4*)&Bs[kk][col0 + 32];
#pragma unroll
            for (int i = 0; i < 8; i++)
#pragma unroll
                for (int j = 0; j < 8; j++)
                    acc[i][j] = fmaf(a[i], b[j], acc[i][j]);
        }
        __syncthreads();
    }
#pragma unroll
    for (int i = 0; i < 8; i++) {
        int r = m0 + row0 + (i < 4 ? i : i + 12);
        float4 v0 = make_float4(acc[i][0], acc[i][1], acc[i][2], acc[i][3]);
        float4 v1 = make_float4(acc[i][4], acc[i][5], acc[i][6], acc[i][7]);
        *(float4*)&C[(size_t)r * N + n0 + col0]      = v0;
        *(float4*)&C[(size_t)r * N + n0 + col0 + 32] = v1;
    }
}

// ---------------- RoPE + scatter qkv -> q/k/v [B,H,S,HD] ----------------
__global__ void __launch_bounds__(256) rope_kernel(const float* __restrict__ sinb,
                                                   const float* __restrict__ cosb) {
    int idx = blockIdx.x * 256 + threadIdx.x;   // over B*S*H*HD = 4194304
    int d = idx & 63;
    int h = (idx >> 6) & 15;
    int s = (idx >> 10) & (S_ - 1);
    int b = idx >> 21;
    size_t base = ((size_t)(b * S_ + s)) * (3 * TD_) + h * HD_;
    float cv = cosb[s * HD_ + d];
    float sv = sinb[s * HD_ + d];
    int   dp  = (d < 32) ? d + 32 : d - 32;
    float sgn = (d < 32) ? -1.f : 1.f;
    float qv  = g_qkv[base + d],          q2 = g_qkv[base + dp];
    float kv  = g_qkv[base + TD_ + d],    k2 = g_qkv[base + TD_ + dp];
    size_t oidx = (((size_t)(b * H_ + h)) * S_ + s) * HD_ + d;
    g_q[oidx] = fmaf(qv, cv, sgn * q2 * sv);
    g_k[oidx] = fmaf(kv, cv, sgn * k2 * sv);
    g_v[oidx] = g_qkv[base + 2 * TD_ + d];
}

// ---------------- flash attention (fp32), 128q x 128k tiles ----------------
#define ATTN_SMEM_FLOATS (128 * 65 * 3 + 128 * 129 + 256)
#define ATTN_SMEM_BYTES  (ATTN_SMEM_FLOATS * 4)

__global__ void __launch_bounds__(256, 1) attn_kernel() {
    extern __shared__ float sm[];
    float* Qs  = sm;                 // [128][65]
    float* Ks  = Qs + 128 * 65;      // [128][65]
    float* Vs  = Ks + 128 * 65;      // [128][65]
    float* Ps  = Vs + 128 * 65;      // [128][129]
    float* red = Ps + 128 * 129;     // [2][128] (max, then sum)

    const int qt = blockIdx.x, bh = blockIdx.y;
    const int b = bh >> 4, h = bh & 15;
    const int len = g_len[b];
    const int qbase = qt * 128;
    const float* qp = g_q + (size_t)bh * S_ * HD_;
    const float* kp = g_k + (size_t)bh * S_ * HD_;
    const float* vp = g_v + (size_t)bh * S_ * HD_;

    const int tid  = threadIdx.x;
    const int warp = tid >> 5, lane = tid & 31;
    const int wm = warp & 3, wn = warp >> 2;
    const int lm = lane >> 3, ln = lane & 7;
    const int row0  = wm * 32 + lm * 4;     // q rows +{0..3}, +16
    const int col0k = wn * 64 + ln * 4;     // score cols +{0..3}, +32
    const int col0d = wn * 32 + ln * 4;     // O cols (4 per thread)

    // load Q tile (128 x 64)
    for (int i = tid; i < 128 * 16; i += 256) {
        int r = i >> 4, d4 = (i & 15) << 2;
        float4 t = *(const float4*)&qp[(size_t)(qbase + r) * HD_ + d4];
        float* dst = &Qs[r * 65 + d4];
        dst[0] = t.x; dst[1] = t.y; dst[2] = t.z; dst[3] = t.w;
    }

    float m_r[8], l_r[8], o[8][4];
#pragma unroll
    for (int i = 0; i < 8; i++) {
        m_r[i] = -INFINITY; l_r[i] = 0.f;
#pragma unroll
        for (int j = 0; j < 4; j++) o[i][j] = 0.f;
    }

    int nkt = qt + 1;
    int lkt = (len + 127) >> 7;
    if (lkt < nkt) nkt = lkt;

    for (int kt = 0; kt < nkt; kt++) {
        const int kb = kt * 128;
        __syncthreads();   // protect Ks/Vs vs previous PV (and Q load at kt=0)
        for (int i = tid; i < 128 * 16; i += 256) {
            int r = i >> 4, d4 = (i & 15) << 2;
            float4 tk = *(const float4*)&kp[(size_t)(kb + r) * HD_ + d4];
            float* dk = &Ks[r * 65 + d4];
            dk[0] = tk.x; dk[1] = tk.y; dk[2] = tk.z; dk[3] = tk.w;
            float4 tv = *(const float4*)&vp[(size_t)(kb + r) * HD_ + d4];
            float* dv = &Vs[r * 65 + d4];
            dv[0] = tv.x; dv[1] = tv.y; dv[2] = tv.z; dv[3] = tv.w;
        }
        __syncthreads();

        // scores S = Q K^T over d=64
        float s[8][8];
#pragma unroll
        for (int i = 0; i < 8; i++)
#pragma unroll
            for (int j = 0; j < 8; j++) s[i][j] = 0.f;
#pragma unroll 8
        for (int d = 0; d < 64; d++) {
            float a[8], bb[8];
#pragma unroll
            for (int i = 0; i < 8; i++) a[i]  = Qs[(row0 + (i < 4 ? i : i + 12)) * 65 + d];
#pragma unroll
            for (int j = 0; j < 8; j++) bb[j] = Ks[(col0k + (j < 4 ? j : j + 28)) * 65 + d];
#pragma unroll
            for (int i = 0; i < 8; i++)
#pragma unroll
                for (int j = 0; j < 8; j++)
                    s[i][j] = fmaf(a[i], bb[j], s[i][j]);
        }

        // mask + scale + row max (thread -> 8 lanes -> cross-warp)
        const float scale = 0.125f;   // 1/sqrt(64)
        float tmax[8];
#pragma unroll
        for (int i = 0; i < 8; i++) {
            int rg = qbase + row0 + (i < 4 ? i : i + 12);
            float mx = -INFINITY;
#pragma unroll
            for (int j = 0; j < 8; j++) {
                int cg = kb + col0k + (j < 4 ? j : j + 28);
                float v = (cg <= rg && cg < len) ? s[i][j] * scale : -INFINITY;
                s[i][j] = v;
                mx = fmaxf(mx, v);
            }
            tmax[i] = mx;
        }
#pragma unroll
        for (int i = 0; i < 8; i++) {
            tmax[i] = fmaxf(tmax[i], __shfl_xor_sync(0xffffffffu, tmax[i], 1));
            tmax[i] = fmaxf(tmax[i], __shfl_xor_sync(0xffffffffu, tmax[i], 2));
            tmax[i] = fmaxf(tmax[i], __shfl_xor_sync(0xffffffffu, tmax[i], 4));
        }
        if (ln == 0) {
#pragma unroll
            for (int i = 0; i < 8; i++)
                red[wn * 128 + row0 + (i < 4 ? i : i + 12)] = tmax[i];
        }
        __syncthreads();
        float mnew[8], corr[8];
#pragma unroll
        for (int i = 0; i < 8; i++) {
            int rr = row0 + (i < 4 ? i : i + 12);
            float cmb = fmaxf(red[rr], red[128 + rr]);
            mnew[i] = fmaxf(m_r[i], cmb);
            corr[i] = __expf(m_r[i] - mnew[i]);   // -inf - finite -> 0; mnew never -inf
            m_r[i]  = mnew[i];
        }
        __syncthreads();   // all reads of red(max) done before red(sum) writes

        float tsum[8];
#pragma unroll
        for (int i = 0; i < 8; i++) {
            int rr = row0 + (i < 4 ? i : i + 12);
            float sum = 0.f;
#pragma unroll
            for (int j = 0; j < 8; j++) {
                float p = __expf(s[i][j] - mnew[i]);
                Ps[rr * 129 + col0k + (j < 4 ? j : j + 28)] = p;
                sum += p;
            }
            tsum[i] = sum;
        }
#pragma unroll
        for (int i = 0; i < 8; i++) {
            tsum[i] += __shfl_xor_sync(0xffffffffu, tsum[i], 1);
            tsum[i] += __shfl_xor_sync(0xffffffffu, tsum[i], 2);
            tsum[i] += __shfl_xor_sync(0xffffffffu, tsum[i], 4);
        }
        if (ln == 0) {
#pragma unroll
            for (int i = 0; i < 8; i++)
                red[wn * 128 + row0 + (i < 4 ? i : i + 12)] = tsum[i];
        }
        __syncthreads();   // also publishes Ps before PV
#pragma unroll
        for (int i = 0; i < 8; i++) {
            int rr = row0 + (i < 4 ? i : i + 12);
            l_r[i] = l_r[i] * corr[i] + (red[rr] + red[128 + rr]);
#pragma unroll
            for (int j = 0; j < 4; j++) o[i][j] *= corr[i];
        }

        // O += P * V   (128-deep)
#pragma unroll 4
        for (int kk = 0; kk < 128; kk++) {
            float pa[8], vb[4];
#pragma unroll
            for (int i = 0; i < 8; i++) pa[i] = Ps[(row0 + (i < 4 ? i : i + 12)) * 129 + kk];
#pragma unroll
            for (int j = 0; j < 4; j++) vb[j] = Vs[kk * 65 + col0d + j];
#pragma unroll
            for (int i = 0; i < 8; i++)
#pragma unroll
                for (int j = 0; j < 4; j++)
                    o[i][j] = fmaf(pa[i], vb[j], o[i][j]);
        }
    }

    // normalize + write [B,S,H*HD]
#pragma unroll
    for (int i = 0; i < 8; i++) {
        int r = qbase + row0 + (i < 4 ? i : i + 12);
        float inv = 1.f / l_r[i];
        float4 ov = make_float4(o[i][0] * inv, o[i][1] * inv, o[i][2] * inv, o[i][3] * inv);
        *(float4*)&g_attn[((size_t)b * S_ + r) * TD_ + h * HD_ + col0d] = ov;
    }
}

// ---------------- launch ----------------
extern "C" void kernel_launch(void* const* d_in, const int* in_sizes, int n_in,
                              void* d_out, int out_size) {
    const float* query = (const float*)d_in[0];
    const float* W_in  = (const float*)d_in[1];
    const float* W_out = (const float*)d_in[2];
    const float* sinb  = (const float*)d_in[3];
    const float* cosb  = (const float*)d_in[4];
    const unsigned char* mask = (const unsigned char*)d_in[5];
    float* out = (float*)d_out;

    void *p_qkv = nullptr, *p_attn = nullptr;
    cudaGetSymbolAddress(&p_qkv, g_qkv);
    cudaGetSymbolAddress(&p_attn, g_attn);
    cudaFuncSetAttribute(attn_kernel, cudaFuncAttributeMaxDynamicSharedMemorySize,
                         ATTN_SMEM_BYTES);

    lengths_kernel<<<1, 256>>>(mask);

    // QKV projection: [4096,1024] x [3072,1024]^T -> [4096,3072]
    gemm_nt<<<dim3(3 * TD_ / 128, B_ * S_ / 128), 256>>>(
        query, W_in, (float*)p_qkv, B_ * S_, 3 * TD_, DM_);

    // RoPE + scatter to [B,H,S,HD]
    rope_kernel<<<(B_ * S_ * H_ * HD_) / 256, 256>>>(sinb, cosb);

    // causal flash attention
    attn_kernel<<<dim3(S_ / 128, B_ * H_), 256, ATTN_SMEM_BYTES>>>();

    // output projection: [4096,1024] x [1024,1024]^T -> d_out
    gemm_nt<<<dim3(DM_ / 128, B_ * S_ / 128), 256>>>(
        (const float*)p_attn, W_out, out, B_ * S_, DM_, TD_);
}

// round 4
// speedup vs baseline: 1.4474x; 1.4474x over previous
#include <cuda_runtime.h>
#include <math.h>
#include <stdint.h>

#define B_ 2
#define S_ 2048
#define DM_ 1024
#define TD_ 1024
#define H_ 16
#define HD_ 64

// ---------------- scratch (static __device__: no allocation) ----------------
__device__ float g_qkv[(size_t)B_ * S_ * 3 * TD_];       // [B*S, 3072]
__device__ float g_q[(size_t)B_ * H_ * S_ * HD_];        // [B,H,S,HD]
__device__ float g_k[(size_t)B_ * H_ * S_ * HD_];
__device__ float g_v[(size_t)B_ * H_ * S_ * HD_];
__device__ float g_attn[(size_t)B_ * S_ * TD_];          // [B*S, 1024]
__device__ int   g_len[B_];

// ---------------- helpers ----------------
__device__ __forceinline__ float tf32r(float x) {
    uint32_t u;
    asm("cvt.rna.tf32.f32 %0, %1;" : "=r"(u) : "f"(x));
    return __uint_as_float(u);
}

__device__ __forceinline__ void mma_tf32(float c[4],
                                         uint32_t a0, uint32_t a1, uint32_t a2, uint32_t a3,
                                         uint32_t b0, uint32_t b1) {
    asm volatile(
        "mma.sync.aligned.m16n8k8.row.col.f32.tf32.tf32.f32 "
        "{%0,%1,%2,%3}, {%4,%5,%6,%7}, {%8,%9}, {%0,%1,%2,%3};"
        : "+f"(c[0]), "+f"(c[1]), "+f"(c[2]), "+f"(c[3])
        : "r"(a0), "r"(a1), "r"(a2), "r"(a3), "r"(b0), "r"(b1));
}

// ---------------- lengths from padding mask (dtype-sniffing) ----------------
__global__ void lengths_kernel(const unsigned char* __restrict__ mask) {
    int tid = threadIdx.x;
    if (tid < B_) g_len[tid] = 0;
    __syncthreads();
    int mode;
    if (mask[1] != 0) mode = 0;                                  // 1-byte bool
    else if (mask[2] == 0x80 && mask[3] == 0x3f) mode = 3;       // float32
    else if (mask[4] != 0) mode = 1;                             // int32
    else mode = 2;                                               // int64
    int c0 = 0, c1 = 0;
    for (int i = tid; i < B_ * S_; i += blockDim.x) {
        bool v;
        switch (mode) {
            case 0:  v = mask[i] != 0; break;
            case 1:  v = ((const int*)mask)[i] != 0; break;
            case 2:  v = ((const long long*)mask)[i] != 0LL; break;
            default: v = ((const float*)mask)[i] != 0.0f; break;
        }
        if (i < S_) c0 += v ? 1 : 0; else c1 += v ? 1 : 0;
    }
    if (c0) atomicAdd(&g_len[0], c0);
    if (c1) atomicAdd(&g_len[1], c1);
}

// ---------------- NT tf32 MMA GEMM: C[M,N] = A[M,K] * B[N,K]^T ----------------
// 128x128 CTA tile, K-chunk 32, 8 warps (2m x 4n), warp tile 64x32.
// Smem stride 36 floats: fragment LDS bank = (4*row + kcol) % 32, conflict-free.
__global__ void __launch_bounds__(256) gemm_tf32(const float* __restrict__ A,
                                                 const float* __restrict__ Bm,
                                                 float* __restrict__ C,
                                                 int M, int N, int K) {
    __shared__ float As[128][36];
    __shared__ float Bs[128][36];
    const int tid = threadIdx.x, lane = tid & 31, warp = tid >> 5;
    const int wm = warp >> 2, wn = warp & 3;
    const int m0 = blockIdx.y * 128, n0 = blockIdx.x * 128;
    const int lr = tid >> 3, lc = (tid & 7) * 4;
    const float* Ap = A  + (size_t)(m0 + lr) * K + lc;
    const float* Bp = Bm + (size_t)(n0 + lr) * K + lc;

    float acc[4][4][4];
#pragma unroll
    for (int mi = 0; mi < 4; mi++)
#pragma unroll
        for (int ni = 0; ni < 4; ni++)
#pragma unroll
            for (int e = 0; e < 4; e++) acc[mi][ni][e] = 0.f;

    float4 pa[4], pb[4];
#pragma unroll
    for (int i = 0; i < 4; i++) {
        pa[i] = *(const float4*)(Ap + (size_t)i * 32 * K);
        pb[i] = *(const float4*)(Bp + (size_t)i * 32 * K);
    }

    const int nkt = K >> 5;
    for (int kt = 0; kt < nkt; kt++) {
#pragma unroll
        for (int i = 0; i < 4; i++) {
            *(float4*)&As[lr + i * 32][lc] =
                make_float4(tf32r(pa[i].x), tf32r(pa[i].y), tf32r(pa[i].z), tf32r(pa[i].w));
            *(float4*)&Bs[lr + i * 32][lc] =
                make_float4(tf32r(pb[i].x), tf32r(pb[i].y), tf32r(pb[i].z), tf32r(pb[i].w));
        }
        __syncthreads();
        if (kt + 1 < nkt) {
            const int ko = (kt + 1) * 32;
#pragma unroll
            for (int i = 0; i < 4; i++) {
                pa[i] = *(const float4*)(Ap + (size_t)i * 32 * K + ko);
                pb[i] = *(const float4*)(Bp + (size_t)i * 32 * K + ko);
            }
        }
#pragma unroll
        for (int ks = 0; ks < 4; ks++) {
            const int k = ks * 8 + (lane & 3);
            uint32_t af[4][4];
#pragma unroll
            for (int mi = 0; mi < 4; mi++) {
                int r = wm * 64 + mi * 16 + (lane >> 2);
                af[mi][0] = __float_as_uint(As[r][k]);
                af[mi][1] = __float_as_uint(As[r + 8][k]);
                af[mi][2] = __float_as_uint(As[r][k + 4]);
                af[mi][3] = __float_as_uint(As[r + 8][k + 4]);
            }
#pragma unroll
            for (int ni = 0; ni < 4; ni++) {
                int c = wn * 32 + ni * 8 + (lane >> 2);
                uint32_t b0 = __float_as_uint(Bs[c][k]);
                uint32_t b1 = __float_as_uint(Bs[c][k + 4]);
#pragma unroll
                for (int mi = 0; mi < 4; mi++)
                    mma_tf32(acc[mi][ni], af[mi][0], af[mi][1], af[mi][2], af[mi][3], b0, b1);
            }
        }
        __syncthreads();
    }

#pragma unroll
    for (int mi = 0; mi < 4; mi++) {
        int r = m0 + wm * 64 + mi * 16 + (lane >> 2);
#pragma unroll
        for (int ni = 0; ni < 4; ni++) {
            int c = n0 + wn * 32 + ni * 8 + (lane & 3) * 2;
            *(float2*)&C[(size_t)r * N + c]       = make_float2(acc[mi][ni][0], acc[mi][ni][1]);
            *(float2*)&C[(size_t)(r + 8) * N + c] = make_float2(acc[mi][ni][2], acc[mi][ni][3]);
        }
    }
}

// ---------------- RoPE + scatter qkv -> q/k/v [B,H,S,HD] ----------------
__global__ void __launch_bounds__(256) rope_kernel(const float* __restrict__ sinb,
                                                   const float* __restrict__ cosb) {
    int idx = blockIdx.x * 256 + threadIdx.x;   // over B*S*H*HD = 4194304
    int d = idx & 63;
    int h = (idx >> 6) & 15;
    int s = (idx >> 10) & (S_ - 1);
    int b = idx >> 21;
    size_t base = ((size_t)(b * S_ + s)) * (3 * TD_) + h * HD_;
    float cv = cosb[s * HD_ + d];
    float sv = sinb[s * HD_ + d];
    int   dp  = (d < 32) ? d + 32 : d - 32;
    float sgn = (d < 32) ? -1.f : 1.f;
    float qv  = g_qkv[base + d],          q2 = g_qkv[base + dp];
    float kv  = g_qkv[base + TD_ + d],    k2 = g_qkv[base + TD_ + dp];
    size_t oidx = (((size_t)(b * H_ + h)) * S_ + s) * HD_ + d;
    g_q[oidx] = fmaf(qv, cv, sgn * q2 * sv);
    g_k[oidx] = fmaf(kv, cv, sgn * k2 * sv);
    g_v[oidx] = g_qkv[base + 2 * TD_ + d];
}

// ---------------- flash attention (tf32 MMA), 128q x 128k tiles ----------------
// smem layout (floats): Qs[128][68], Ks[128][68], Vst[64][132], Ps[128][132], red[4][128]
#define QS_OFF   0
#define KS_OFF   (128 * 68)
#define VST_OFF  (2 * 128 * 68)
#define PS_OFF   (VST_OFF + 64 * 132)
#define RED_OFF  (PS_OFF + 128 * 132)
#define ATTN_SMEM_FLOATS (RED_OFF + 4 * 128)
#define ATTN_SMEM_BYTES  (ATTN_SMEM_FLOATS * 4)

__global__ void __launch_bounds__(256, 1) attn_tf32() {
    extern __shared__ float sm[];
    float (*Qs)[68]   = (float(*)[68])(sm + QS_OFF);
    float (*Ks)[68]   = (float(*)[68])(sm + KS_OFF);
    float (*Vst)[132] = (float(*)[132])(sm + VST_OFF);
    float (*Ps)[132]  = (float(*)[132])(sm + PS_OFF);
    float* red        = sm + RED_OFF;   // [4][128]

    const int qt = blockIdx.x, bh = blockIdx.y;
    const int b = bh >> 4, h = bh & 15;
    const int len = g_len[b];
    const int qbase = qt * 128;
    const float* qp = g_q + (size_t)bh * S_ * HD_;
    const float* kp = g_k + (size_t)bh * S_ * HD_;
    const float* vp = g_v + (size_t)bh * S_ * HD_;

    const int tid = threadIdx.x, lane = tid & 31, warp = tid >> 5;
    const int wm = warp >> 2, wn = warp & 3;      // 2(m) x 4(n)
    const int qr = lane >> 2, qc = lane & 3;      // quad row / quad col

    // load Q tile (pre-scaled by 1/sqrt(64), tf32-converted)
    for (int i = tid; i < 2048; i += 256) {
        int r = i >> 4, d4 = (i & 15) << 2;
        float4 t = *(const float4*)&qp[(size_t)(qbase + r) * HD_ + d4];
        *(float4*)&Qs[r][d4] = make_float4(tf32r(t.x * 0.125f), tf32r(t.y * 0.125f),
                                           tf32r(t.z * 0.125f), tf32r(t.w * 0.125f));
    }

    float m_r[4][2], l_r[4][2], o[4][2][4];
#pragma unroll
    for (int mi = 0; mi < 4; mi++) {
        m_r[mi][0] = -INFINITY; m_r[mi][1] = -INFINITY;
        l_r[mi][0] = 0.f;       l_r[mi][1] = 0.f;
#pragma unroll
        for (int ni = 0; ni < 2; ni++)
#pragma unroll
            for (int e = 0; e < 4; e++) o[mi][ni][e] = 0.f;
    }

    int nkt = qt + 1;
    int lkt = (len + 127) >> 7;
    if (lkt < nkt) nkt = lkt;

    for (int kt = 0; kt < nkt; kt++) {
        const int kb = kt * 128;
        __syncthreads();   // protect Ks/Vst/Ps vs previous iteration reads (and Qs at kt=0)
        // K tile (tf32)
        for (int i = tid; i < 2048; i += 256) {
            int r = i >> 4, d4 = (i & 15) << 2;
            float4 t = *(const float4*)&kp[(size_t)(kb + r) * HD_ + d4];
            *(float4*)&Ks[r][d4] = make_float4(tf32r(t.x), tf32r(t.y), tf32r(t.z), tf32r(t.w));
        }
        // V tile transposed -> Vst[d][key] (tf32); mapping keeps STS conflict-free
        for (int i = tid; i < 2048; i += 256) {
            int key = (i & 31) | ((i >> 9) << 5);
            int d4  = ((i >> 5) & 15) << 2;
            float4 t = *(const float4*)&vp[(size_t)(kb + key) * HD_ + d4];
            Vst[d4 + 0][key] = tf32r(t.x);
            Vst[d4 + 1][key] = tf32r(t.y);
            Vst[d4 + 2][key] = tf32r(t.z);
            Vst[d4 + 3][key] = tf32r(t.w);
        }
        __syncthreads();

        // ---- scores S = Q K^T (d = 64, 8 MMA k-steps) ----
        float sf[4][4][4];
#pragma unroll
        for (int mi = 0; mi < 4; mi++)
#pragma unroll
            for (int ni = 0; ni < 4; ni++)
#pragma unroll
                for (int e = 0; e < 4; e++) sf[mi][ni][e] = 0.f;

#pragma unroll
        for (int ks = 0; ks < 8; ks++) {
            const int k = ks * 8 + qc;
            uint32_t af[4][4];
#pragma unroll
            for (int mi = 0; mi < 4; mi++) {
                int r = wm * 64 + mi * 16 + qr;
                af[mi][0] = __float_as_uint(Qs[r][k]);
                af[mi][1] = __float_as_uint(Qs[r + 8][k]);
                af[mi][2] = __float_as_uint(Qs[r][k + 4]);
                af[mi][3] = __float_as_uint(Qs[r + 8][k + 4]);
            }
#pragma unroll
            for (int ni = 0; ni < 4; ni++) {
                int c = wn * 32 + ni * 8 + qr;
                uint32_t b0 = __float_as_uint(Ks[c][k]);
                uint32_t b1 = __float_as_uint(Ks[c][k + 4]);
#pragma unroll
                for (int mi = 0; mi < 4; mi++)
                    mma_tf32(sf[mi][ni], af[mi][0], af[mi][1], af[mi][2], af[mi][3], b0, b1);
            }
        }

        // ---- mask + row max ----
        float tmax[4][2];
#pragma unroll
        for (int mi = 0; mi < 4; mi++) {
            int rl = qbase + wm * 64 + mi * 16 + qr;
            int rh = rl + 8;
            float mx0 = -INFINITY, mx1 = -INFINITY;
#pragma unroll
            for (int ni = 0; ni < 4; ni++) {
                int c0 = kb + wn * 32 + ni * 8 + qc * 2;
                int c1 = c0 + 1;
                if (c0 > rl || c0 >= len) sf[mi][ni][0] = -INFINITY;
                if (c1 > rl || c1 >= len) sf[mi][ni][1] = -INFINITY;
                if (c0 > rh || c0 >= len) sf[mi][ni][2] = -INFINITY;
                if (c1 > rh || c1 >= len) sf[mi][ni][3] = -INFINITY;
                mx0 = fmaxf(mx0, fmaxf(sf[mi][ni][0], sf[mi][ni][1]));
                mx1 = fmaxf(mx1, fmaxf(sf[mi][ni][2], sf[mi][ni][3]));
            }
            mx0 = fmaxf(mx0, __shfl_xor_sync(0xffffffffu, mx0, 1));
            mx0 = fmaxf(mx0, __shfl_xor_sync(0xffffffffu, mx0, 2));
            mx1 = fmaxf(mx1, __shfl_xor_sync(0xffffffffu, mx1, 1));
            mx1 = fmaxf(mx1, __shfl_xor_sync(0xffffffffu, mx1, 2));
            tmax[mi][0] = mx0; tmax[mi][1] = mx1;
        }
        if (qc == 0) {
#pragma unroll
            for (int mi = 0; mi < 4; mi++) {
                int rr = wm * 64 + mi * 16 + qr;
                red[wn * 128 + rr]     = tmax[mi][0];
                red[wn * 128 + rr + 8] = tmax[mi][1];
            }
        }
        __syncthreads();

        float mnew[4][2], corr[4][2];
#pragma unroll
        for (int mi = 0; mi < 4; mi++) {
#pragma unroll
            for (int hf = 0; hf < 2; hf++) {
                int rr = wm * 64 + mi * 16 + qr + hf * 8;
                float cmb = fmaxf(fmaxf(red[rr], red[128 + rr]),
                                  fmaxf(red[256 + rr], red[384 + rr]));
                float mn = fmaxf(m_r[mi][hf], cmb);
                corr[mi][hf] = __expf(m_r[mi][hf] - mn);
                mnew[mi][hf] = mn;
                m_r[mi][hf]  = mn;
            }
        }
        __syncthreads();   // red(max) reads done before red(sum) writes

        // ---- exp, store P (tf32) to smem, row sums ----
        float tsum[4][2];
#pragma unroll
        for (int mi = 0; mi < 4; mi++) { tsum[mi][0] = 0.f; tsum[mi][1] = 0.f; }
#pragma unroll
        for (int mi = 0; mi < 4; mi++) {
            int rl = wm * 64 + mi * 16 + qr;
#pragma unroll
            for (int ni = 0; ni < 4; ni++) {
                int c0 = wn * 32 + ni * 8 + qc * 2;
                float p0 = __expf(sf[mi][ni][0] - mnew[mi][0]);
                float p1 = __expf(sf[mi][ni][1] - mnew[mi][0]);
                float p2 = __expf(sf[mi][ni][2] - mnew[mi][1]);
                float p3 = __expf(sf[mi][ni][3] - mnew[mi][1]);
                tsum[mi][0] += p0 + p1;
                tsum[mi][1] += p2 + p3;
                *(float2*)&Ps[rl][c0]     = make_float2(tf32r(p0), tf32r(p1));
                *(float2*)&Ps[rl + 8][c0] = make_float2(tf32r(p2), tf32r(p3));
            }
            tsum[mi][0] += __shfl_xor_sync(0xffffffffu, tsum[mi][0], 1);
            tsum[mi][0] += __shfl_xor_sync(0xffffffffu, tsum[mi][0], 2);
            tsum[mi][1] += __shfl_xor_sync(0xffffffffu, tsum[mi][1], 1);
            tsum[mi][1] += __shfl_xor_sync(0xffffffffu, tsum[mi][1], 2);
        }
        if (qc == 0) {
#pragma unroll
            for (int mi = 0; mi < 4; mi++) {
                int rr = wm * 64 + mi * 16 + qr;
                red[wn * 128 + rr]     = tsum[mi][0];
                red[wn * 128 + rr + 8] = tsum[mi][1];
            }
        }
        __syncthreads();   // publishes Ps and red(sum)

#pragma unroll
        for (int mi = 0; mi < 4; mi++) {
#pragma unroll
            for (int hf = 0; hf < 2; hf++) {
                int rr = wm * 64 + mi * 16 + qr + hf * 8;
                float s4 = (red[rr] + red[128 + rr]) + (red[256 + rr] + red[384 + rr]);
                l_r[mi][hf] = l_r[mi][hf] * corr[mi][hf] + s4;
            }
#pragma unroll
            for (int ni = 0; ni < 2; ni++) {
                o[mi][ni][0] *= corr[mi][0];
                o[mi][ni][1] *= corr[mi][0];
                o[mi][ni][2] *= corr[mi][1];
                o[mi][ni][3] *= corr[mi][1];
            }
        }

        // ---- O += P V (k = 128 keys, 16 MMA k-steps; warp n-range = 16 d-cols) ----
#pragma unroll
        for (int ks = 0; ks < 16; ks++) {
            const int k = ks * 8 + qc;
            uint32_t af[4][4];
#pragma unroll
            for (int mi = 0; mi < 4; mi++) {
                int r = wm * 64 + mi * 16 + qr;
                af[mi][0] = __float_as_uint(Ps[r][k]);
                af[mi][1] = __float_as_uint(Ps[r + 8][k]);
                af[mi][2] = __float_as_uint(Ps[r][k + 4]);
                af[mi][3] = __float_as_uint(Ps[r + 8][k + 4]);
            }
#pragma unroll
            for (int ni = 0; ni < 2; ni++) {
                int dcol = wn * 16 + ni * 8 + qr;
                uint32_t b0 = __float_as_uint(Vst[dcol][k]);
                uint32_t b1 = __float_as_uint(Vst[dcol][k + 4]);
#pragma unroll
                for (int mi = 0; mi < 4; mi++)
                    mma_tf32(o[mi][ni], af[mi][0], af[mi][1], af[mi][2], af[mi][3], b0, b1);
            }
        }
    }

    // ---- normalize + write [B,S,H*HD] ----
#pragma unroll
    for (int mi = 0; mi < 4; mi++) {
        int rl = qbase + wm * 64 + mi * 16 + qr;
        float inv0 = 1.f / l_r[mi][0];
        float inv1 = 1.f / l_r[mi][1];
#pragma unroll
        for (int ni = 0; ni < 2; ni++) {
            int c = h * HD_ + wn * 16 + ni * 8 + qc * 2;
            *(float2*)&g_attn[((size_t)b * S_ + rl) * TD_ + c] =
                make_float2(o[mi][ni][0] * inv0, o[mi][ni][1] * inv0);
            *(float2*)&g_attn[((size_t)b * S_ + rl + 8) * TD_ + c] =
                make_float2(o[mi][ni][2] * inv1, o[mi][ni][3] * inv1);
        }
    }
}

// ---------------- launch ----------------
extern "C" void kernel_launch(void* const* d_in, const int* in_sizes, int n_in,
                              void* d_out, int out_size) {
    const float* query = (const float*)d_in[0];
    const float* W_in  = (const float*)d_in[1];
    const float* W_out = (const float*)d_in[2];
    const float* sinb  = (const float*)d_in[3];
    const float* cosb  = (const float*)d_in[4];
    const unsigned char* mask = (const unsigned char*)d_in[5];
    float* out = (float*)d_out;

    void *p_qkv = nullptr, *p_attn = nullptr;
    cudaGetSymbolAddress(&p_qkv, g_qkv);
    cudaGetSymbolAddress(&p_attn, g_attn);
    cudaFuncSetAttribute(attn_tf32, cudaFuncAttributeMaxDynamicSharedMemorySize,
                         ATTN_SMEM_BYTES);

    lengths_kernel<<<1, 256>>>(mask);

    // QKV projection: [4096,1024] x [3072,1024]^T -> [4096,3072]
    gemm_tf32<<<dim3(3 * TD_ / 128, B_ * S_ / 128), 256>>>(
        query, W_in, (float*)p_qkv, B_ * S_, 3 * TD_, DM_);

    // RoPE + scatter to [B,H,S,HD]
    rope_kernel<<<(B_ * S_ * H_ * HD_) / 256, 256>>>(sinb, cosb);

    // causal flash attention (tf32 tensor-core)
    attn_tf32<<<dim3(S_ / 128, B_ * H_), 256, ATTN_SMEM_BYTES>>>();

    // output projection: [4096,1024] x [1024,1024]^T -> d_out
    gemm_tf32<<<dim3(DM_ / 128, B_ * S_ / 128), 256>>>(
        (const float*)p_attn, W_out, out, B_ * S_, DM_, TD_);
}

// round 5
// speedup vs baseline: 2.6705x; 1.8451x over previous
#include <cuda_runtime.h>
#include <math.h>
#include <stdint.h>

#define B_ 2
#define S_ 2048
#define DM_ 1024
#define TD_ 1024
#define H_ 16
#define HD_ 64

// ---------------- scratch (static __device__: no allocation) ----------------
__device__ float g_qkv[(size_t)B_ * S_ * 3 * TD_];       // [B*S, 3072]
__device__ float g_q[(size_t)B_ * H_ * S_ * HD_];        // [B,H,S,HD]
__device__ float g_k[(size_t)B_ * H_ * S_ * HD_];
__device__ float g_v[(size_t)B_ * H_ * S_ * HD_];
__device__ float g_attn[(size_t)B_ * S_ * TD_];          // [B*S, 1024]
__device__ int   g_len[B_];

// ---------------- helpers ----------------
__device__ __forceinline__ float tf32r(float x) {
    uint32_t u;
    asm("cvt.rna.tf32.f32 %0, %1;" : "=r"(u) : "f"(x));
    return __uint_as_float(u);
}

__device__ __forceinline__ void mma_tf32(float c[4],
                                         uint32_t a0, uint32_t a1, uint32_t a2, uint32_t a3,
                                         uint32_t b0, uint32_t b1) {
    asm volatile(
        "mma.sync.aligned.m16n8k8.row.col.f32.tf32.tf32.f32 "
        "{%0,%1,%2,%3}, {%4,%5,%6,%7}, {%8,%9}, {%0,%1,%2,%3};"
        : "+f"(c[0]), "+f"(c[1]), "+f"(c[2]), "+f"(c[3])
        : "r"(a0), "r"(a1), "r"(a2), "r"(a3), "r"(b0), "r"(b1));
}

__device__ __forceinline__ void cpa16(float* s, const float* g) {
    uint32_t sa = (uint32_t)__cvta_generic_to_shared(s);
    asm volatile("cp.async.cg.shared.global [%0], [%1], 16;" :: "r"(sa), "l"(g));
}
#define CP_COMMIT() asm volatile("cp.async.commit_group;")
#define CP_WAIT0()  asm volatile("cp.async.wait_group 0;")

// ---------------- lengths from padding mask (dtype-sniffing) ----------------
__global__ void lengths_kernel(const unsigned char* __restrict__ mask) {
    int tid = threadIdx.x;
    if (tid < B_) g_len[tid] = 0;
    __syncthreads();
    int mode;
    if (mask[1] != 0) mode = 0;                                  // 1-byte bool
    else if (mask[2] == 0x80 && mask[3] == 0x3f) mode = 3;       // float32
    else if (mask[4] != 0) mode = 1;                             // int32
    else mode = 2;                                               // int64
    int c0 = 0, c1 = 0;
    for (int i = tid; i < B_ * S_; i += blockDim.x) {
        bool v;
        switch (mode) {
            case 0:  v = mask[i] != 0; break;
            case 1:  v = ((const int*)mask)[i] != 0; break;
            case 2:  v = ((const long long*)mask)[i] != 0LL; break;
            default: v = ((const float*)mask)[i] != 0.0f; break;
        }
        if (i < S_) c0 += v ? 1 : 0; else c1 += v ? 1 : 0;
    }
    if (c0) atomicAdd(&g_len[0], c0);
    if (c1) atomicAdd(&g_len[1], c1);
}

// ---------------- NT tf32 GEMM, cp.async double-buffered ----------------
// C[M,N] = A[M,K] * B[N,K]^T. 128x128 CTA tile, K-chunk 32, 8 warps (2m x 4n).
// Dynamic smem: As[2][128][36], Bs[2][128][36]. Raw fp32 staged; tf32 cvt at use.
#define GEMM_SMEM_FLOATS (4 * 128 * 36)
#define GEMM_SMEM_BYTES  (GEMM_SMEM_FLOATS * 4)

__global__ void __launch_bounds__(256) gemm_tf32(const float* __restrict__ A,
                                                 const float* __restrict__ Bm,
                                                 float* __restrict__ C,
                                                 int M, int N, int K) {
    extern __shared__ float sm[];
    float* As = sm;                    // [2][128][36]
    float* Bs = sm + 2 * 128 * 36;     // [2][128][36]
    const int tid = threadIdx.x, lane = tid & 31, warp = tid >> 5;
    const int wm = warp >> 2, wn = warp & 3;
    const int qr = lane >> 2, qc = lane & 3;
    const int m0 = blockIdx.y * 128, n0 = blockIdx.x * 128;

    float acc[4][4][4];
#pragma unroll
    for (int mi = 0; mi < 4; mi++)
#pragma unroll
        for (int ni = 0; ni < 4; ni++)
#pragma unroll
            for (int e = 0; e < 4; e++) acc[mi][ni][e] = 0.f;

    const int nkt = K >> 5;
    // prologue: chunk 0
#pragma unroll
    for (int i = 0; i < 4; i++) {
        int idx = tid + i * 256;
        int r = idx >> 3, s = (idx & 7) * 4;
        cpa16(As + r * 36 + s, A  + (size_t)(m0 + r) * K + s);
        cpa16(Bs + r * 36 + s, Bm + (size_t)(n0 + r) * K + s);
    }
    CP_COMMIT();

    for (int kt = 0; kt < nkt; kt++) {
        const int buf = kt & 1;
        CP_WAIT0();
        __syncthreads();
        if (kt + 1 < nkt) {
            const int ko = (kt + 1) * 32, nb = buf ^ 1;
#pragma unroll
            for (int i = 0; i < 4; i++) {
                int idx = tid + i * 256;
                int r = idx >> 3, s = (idx & 7) * 4;
                cpa16(As + (nb * 128 + r) * 36 + s, A  + (size_t)(m0 + r) * K + ko + s);
                cpa16(Bs + (nb * 128 + r) * 36 + s, Bm + (size_t)(n0 + r) * K + ko + s);
            }
        }
        CP_COMMIT();
        const float* Ab = As + buf * 128 * 36;
        const float* Bb = Bs + buf * 128 * 36;
#pragma unroll
        for (int ks = 0; ks < 4; ks++) {
            const int k = ks * 8 + qc;
            uint32_t af[4][4];
#pragma unroll
            for (int mi = 0; mi < 4; mi++) {
                const float* ar = Ab + (wm * 64 + mi * 16 + qr) * 36;
                af[mi][0] = __float_as_uint(tf32r(ar[k]));
                af[mi][1] = __float_as_uint(tf32r(ar[8 * 36 + k]));
                af[mi][2] = __float_as_uint(tf32r(ar[k + 4]));
                af[mi][3] = __float_as_uint(tf32r(ar[8 * 36 + k + 4]));
            }
#pragma unroll
            for (int ni = 0; ni < 4; ni++) {
                const float* br = Bb + (wn * 32 + ni * 8 + qr) * 36;
                uint32_t b0 = __float_as_uint(tf32r(br[k]));
                uint32_t b1 = __float_as_uint(tf32r(br[k + 4]));
#pragma unroll
                for (int mi = 0; mi < 4; mi++)
                    mma_tf32(acc[mi][ni], af[mi][0], af[mi][1], af[mi][2], af[mi][3], b0, b1);
            }
        }
    }

#pragma unroll
    for (int mi = 0; mi < 4; mi++) {
        int r = m0 + wm * 64 + mi * 16 + qr;
#pragma unroll
        for (int ni = 0; ni < 4; ni++) {
            int c = n0 + wn * 32 + ni * 8 + qc * 2;
            *(float2*)&C[(size_t)r * N + c]       = make_float2(acc[mi][ni][0], acc[mi][ni][1]);
            *(float2*)&C[(size_t)(r + 8) * N + c] = make_float2(acc[mi][ni][2], acc[mi][ni][3]);
        }
    }
}

// ---------------- RoPE + scatter qkv -> q/k/v [B,H,S,HD] ----------------
__global__ void __launch_bounds__(256) rope_kernel(const float* __restrict__ sinb,
                                                   const float* __restrict__ cosb) {
    int idx = blockIdx.x * 256 + threadIdx.x;   // over B*S*H*HD = 4194304
    int d = idx & 63;
    int h = (idx >> 6) & 15;
    int s = (idx >> 10) & (S_ - 1);
    int b = idx >> 21;
    size_t base = ((size_t)(b * S_ + s)) * (3 * TD_) + h * HD_;
    float cv = cosb[s * HD_ + d];
    float sv = sinb[s * HD_ + d];
    int   dp  = (d < 32) ? d + 32 : d - 32;
    float sgn = (d < 32) ? -1.f : 1.f;
    float qv  = g_qkv[base + d],          q2 = g_qkv[base + dp];
    float kv  = g_qkv[base + TD_ + d],    k2 = g_qkv[base + TD_ + dp];
    size_t oidx = (((size_t)(b * H_ + h)) * S_ + s) * HD_ + d;
    g_q[oidx] = fmaf(qv, cv, sgn * q2 * sv);
    g_k[oidx] = fmaf(kv, cv, sgn * k2 * sv);
    g_v[oidx] = g_qkv[base + 2 * TD_ + d];
}

// ---------------- flash attention v2 (tf32 MMA) ----------------
// 8 warps x 16 q-rows each; each warp spans all 128 keys of the tile.
// Softmax fully warp-local. Key-permutation pi=[0,4,1,5,2,6,3,7] in QK makes
// the score C-fragment identical to the PV A-fragment (P never leaves regs).
// cp.async double-buffered K/V (raw fp32, tf32 cvt at use). One barrier/tile.
// Smem (floats): Qs[128][68], Ks[2][128][68], Vs[2][128][72]
#define AT_QS 0
#define AT_KS (128 * 68)
#define AT_VS (AT_KS + 2 * 128 * 68)
#define ATTN_SMEM_FLOATS (AT_VS + 2 * 128 * 72)
#define ATTN_SMEM_BYTES  (ATTN_SMEM_FLOATS * 4)

__global__ void __launch_bounds__(256, 1) attn_tf32() {
    extern __shared__ float sm[];
    float (*Qs)[68] = (float(*)[68])(sm + AT_QS);
    float* smK = sm + AT_KS;      // [2][128][68]
    float* smV = sm + AT_VS;      // [2][128][72]

    const int qt = blockIdx.x, bh = blockIdx.y;
    const int b = bh >> 4, h = bh & 15;
    const int len = g_len[b];
    const int qbase = qt * 128;
    const float* qp = g_q + (size_t)bh * S_ * HD_;
    const float* kp = g_k + (size_t)bh * S_ * HD_;
    const float* vp = g_v + (size_t)bh * S_ * HD_;

    const int tid = threadIdx.x, lane = tid & 31, w = tid >> 5;
    const int qr = lane >> 2, qc = lane & 3;
    const int piq = (qr & 1) ? (qr >> 1) + 4 : (qr >> 1);   // pi(qr)

    int nkt = qt + 1;
    int lkt = (len + 127) >> 7;
    if (lkt < nkt) nkt = lkt;

    // prologue: cp.async K/V tile 0 (raw fp32)
#pragma unroll
    for (int i = 0; i < 8; i++) {
        int idx = tid + i * 256;
        int r = idx >> 4, s = (idx & 15) * 4;
        cpa16(smK + r * 68 + s, kp + (size_t)r * HD_ + s);
        cpa16(smV + r * 72 + s, vp + (size_t)r * HD_ + s);
    }
    CP_COMMIT();

    // Q tile: scale by 1/sqrt(64) + tf32 round (read many times -> cvt once)
    for (int i = tid; i < 2048; i += 256) {
        int r = i >> 4, d4 = (i & 15) << 2;
        float4 t = *(const float4*)&qp[(size_t)(qbase + r) * HD_ + d4];
        *(float4*)&Qs[r][d4] = make_float4(tf32r(t.x * 0.125f), tf32r(t.y * 0.125f),
                                           tf32r(t.z * 0.125f), tf32r(t.w * 0.125f));
    }

    float m0r = -INFINITY, m1r = -INFINITY, l0 = 0.f, l1 = 0.f;
    float o[8][4];
#pragma unroll
    for (int nd = 0; nd < 8; nd++)
#pragma unroll
        for (int e = 0; e < 4; e++) o[nd][e] = 0.f;

    for (int kt = 0; kt < nkt; kt++) {
        const int buf = kt & 1;
        const int kb = kt * 128;
        CP_WAIT0();
        __syncthreads();
        if (kt + 1 < nkt) {
            const int nb = buf ^ 1, ko = (kt + 1) * 128;
#pragma unroll
            for (int i = 0; i < 8; i++) {
                int idx = tid + i * 256;
                int r = idx >> 4, s = (idx & 15) * 4;
                cpa16(smK + (nb * 128 + r) * 68 + s, kp + (size_t)(ko + r) * HD_ + s);
                cpa16(smV + (nb * 128 + r) * 72 + s, vp + (size_t)(ko + r) * HD_ + s);
            }
        }
        CP_COMMIT();
        const float* Kb = smK + buf * 128 * 68;
        const float* Vb = smV + buf * 128 * 72;

        // ---- QK^T: 16 rows x 128 keys, keys column-permuted by pi ----
        float sf[16][4];
#pragma unroll
        for (int ni = 0; ni < 16; ni++)
#pragma unroll
            for (int e = 0; e < 4; e++) sf[ni][e] = 0.f;

#pragma unroll
        for (int ks = 0; ks < 8; ks++) {
            const int k = ks * 8 + qc;
            const float* ar = Qs[w * 16 + qr];
            uint32_t a0 = __float_as_uint(ar[k]);
            uint32_t a1 = __float_as_uint(ar[8 * 68 + k]);
            uint32_t a2 = __float_as_uint(ar[k + 4]);
            uint32_t a3 = __float_as_uint(ar[8 * 68 + k + 4]);
#pragma unroll
            for (int ni = 0; ni < 16; ni++) {
                const float* kr = Kb + (ni * 8 + piq) * 68;
                uint32_t b0 = __float_as_uint(tf32r(kr[k]));
                uint32_t b1 = __float_as_uint(tf32r(kr[k + 4]));
                mma_tf32(sf[ni], a0, a1, a2, a3, b0, b1);
            }
        }

        // ---- mask + warp-local row max (rows qr, qr+8 of this warp) ----
        // with pi: elements (c0,c2) <-> key ni*8+qc, (c1,c3) <-> key ni*8+qc+4
        const int rl = qbase + w * 16 + qr, rh = rl + 8;
        float mx0 = -INFINITY, mx1 = -INFINITY;
#pragma unroll
        for (int ni = 0; ni < 16; ni++) {
            int k0 = kb + ni * 8 + qc, k1 = k0 + 4;
            if (k0 > rl || k0 >= len) sf[ni][0] = -INFINITY;
            if (k1 > rl || k1 >= len) sf[ni][1] = -INFINITY;
            if (k0 > rh || k0 >= len) sf[ni][2] = -INFINITY;
            if (k1 > rh || k1 >= len) sf[ni][3] = -INFINITY;
            mx0 = fmaxf(mx0, fmaxf(sf[ni][0], sf[ni][1]));
            mx1 = fmaxf(mx1, fmaxf(sf[ni][2], sf[ni][3]));
        }
        mx0 = fmaxf(mx0, __shfl_xor_sync(0xffffffffu, mx0, 1));
        mx0 = fmaxf(mx0, __shfl_xor_sync(0xffffffffu, mx0, 2));
        mx1 = fmaxf(mx1, __shfl_xor_sync(0xffffffffu, mx1, 1));
        mx1 = fmaxf(mx1, __shfl_xor_sync(0xffffffffu, mx1, 2));

        float mn0 = fmaxf(m0r, mx0), mn1 = fmaxf(m1r, mx1);
        float corr0 = __expf(m0r - mn0), corr1 = __expf(m1r - mn1);
        m0r = mn0; m1r = mn1;

        // ---- exp + row sum; P (tf32-rounded) kept in sf regs ----
        float s0 = 0.f, s1 = 0.f;
#pragma unroll
        for (int ni = 0; ni < 16; ni++) {
            float p0 = __expf(sf[ni][0] - mn0);
            float p1 = __expf(sf[ni][1] - mn0);
            float p2 = __expf(sf[ni][2] - mn1);
            float p3 = __expf(sf[ni][3] - mn1);
            s0 += p0 + p1; s1 += p2 + p3;
            sf[ni][0] = tf32r(p0); sf[ni][1] = tf32r(p1);
            sf[ni][2] = tf32r(p2); sf[ni][3] = tf32r(p3);
        }
        s0 += __shfl_xor_sync(0xffffffffu, s0, 1);
        s0 += __shfl_xor_sync(0xffffffffu, s0, 2);
        s1 += __shfl_xor_sync(0xffffffffu, s1, 1);
        s1 += __shfl_xor_sync(0xffffffffu, s1, 2);
        l0 = l0 * corr0 + s0;
        l1 = l1 * corr1 + s1;
#pragma unroll
        for (int nd = 0; nd < 8; nd++) {
            o[nd][0] *= corr0; o[nd][1] *= corr0;
            o[nd][2] *= corr1; o[nd][3] *= corr1;
        }

        // ---- O += P V: A-fragment straight from score regs (pi trick) ----
#pragma unroll
        for (int ks2 = 0; ks2 < 16; ks2++) {
            uint32_t a0 = __float_as_uint(sf[ks2][0]);   // (row qr,  key qc)
            uint32_t a1 = __float_as_uint(sf[ks2][2]);   // (row qr+8,key qc)
            uint32_t a2 = __float_as_uint(sf[ks2][1]);   // (row qr,  key qc+4)
            uint32_t a3 = __float_as_uint(sf[ks2][3]);   // (row qr+8,key qc+4)
            const float* v0 = Vb + (ks2 * 8 + qc) * 72;
            const float* v1 = v0 + 4 * 72;
#pragma unroll
            for (int nd = 0; nd < 8; nd++) {
                int dcol = nd * 8 + qr;
                uint32_t b0 = __float_as_uint(tf32r(v0[dcol]));
                uint32_t b1 = __float_as_uint(tf32r(v1[dcol]));
                mma_tf32(o[nd], a0, a1, a2, a3, b0, b1);
            }
        }
    }

    // ---- normalize + write [B,S,H*HD] ----
    const float inv0 = 1.f / l0, inv1 = 1.f / l1;
    const int rl = qbase + w * 16 + qr;
#pragma unroll
    for (int nd = 0; nd < 8; nd++) {
        int c = h * HD_ + nd * 8 + qc * 2;
        *(float2*)&g_attn[((size_t)b * S_ + rl) * TD_ + c] =
            make_float2(o[nd][0] * inv0, o[nd][1] * inv0);
        *(float2*)&g_attn[((size_t)b * S_ + rl + 8) * TD_ + c] =
            make_float2(o[nd][2] * inv1, o[nd][3] * inv1);
    }
}

// ---------------- launch ----------------
extern "C" void kernel_launch(void* const* d_in, const int* in_sizes, int n_in,
                              void* d_out, int out_size) {
    const float* query = (const float*)d_in[0];
    const float* W_in  = (const float*)d_in[1];
    const float* W_out = (const float*)d_in[2];
    const float* sinb  = (const float*)d_in[3];
    const float* cosb  = (const float*)d_in[4];
    const unsigned char* mask = (const unsigned char*)d_in[5];
    float* out = (float*)d_out;

    void *p_qkv = nullptr, *p_attn = nullptr;
    cudaGetSymbolAddress(&p_qkv, g_qkv);
    cudaGetSymbolAddress(&p_attn, g_attn);
    cudaFuncSetAttribute(attn_tf32, cudaFuncAttributeMaxDynamicSharedMemorySize,
                         ATTN_SMEM_BYTES);
    cudaFuncSetAttribute(gemm_tf32, cudaFuncAttributeMaxDynamicSharedMemorySize,
                         GEMM_SMEM_BYTES);

    lengths_kernel<<<1, 256>>>(mask);

    // QKV projection: [4096,1024] x [3072,1024]^T -> [4096,3072]
    gemm_tf32<<<dim3(3 * TD_ / 128, B_ * S_ / 128), 256, GEMM_SMEM_BYTES>>>(
        query, W_in, (float*)p_qkv, B_ * S_, 3 * TD_, DM_);

    // RoPE + scatter to [B,H,S,HD]
    rope_kernel<<<(B_ * S_ * H_ * HD_) / 256, 256>>>(sinb, cosb);

    // causal flash attention (tf32 tensor-core, warp-local softmax)
    attn_tf32<<<dim3(S_ / 128, B_ * H_), 256, ATTN_SMEM_BYTES>>>();

    // output projection: [4096,1024] x [1024,1024]^T -> d_out
    gemm_tf32<<<dim3(DM_ / 128, B_ * S_ / 128), 256, GEMM_SMEM_BYTES>>>(
        (const float*)p_attn, W_out, out, B_ * S_, DM_, TD_);
}

// round 6
// speedup vs baseline: 3.0543x; 1.1437x over previous
#include <cuda_runtime.h>
#include <math.h>
#include <stdint.h>

#define B_ 2
#define S_ 2048
#define DM_ 1024
#define TD_ 1024
#define H_ 16
#define HD_ 64

// ---------------- scratch (static __device__: no allocation) ----------------
__device__ float g_qkv[(size_t)B_ * S_ * 3 * TD_];       // [B*S, 3072]
__device__ float g_q[(size_t)B_ * H_ * S_ * HD_];        // [B,H,S,HD] (tf32-rounded)
__device__ float g_k[(size_t)B_ * H_ * S_ * HD_];        // (tf32-rounded)
__device__ float g_v[(size_t)B_ * H_ * S_ * HD_];        // (tf32-rounded)
__device__ float g_attn[(size_t)B_ * S_ * TD_];          // [B*S, 1024] (tf32-rounded)
__device__ float g_qt[(size_t)B_ * S_ * DM_];            // tf32-rounded query
__device__ float g_wi[(size_t)3 * TD_ * DM_];            // tf32-rounded W_in
__device__ float g_wo[(size_t)DM_ * TD_];                // tf32-rounded W_out
__device__ int   g_len[B_];

// ---------------- helpers ----------------
__device__ __forceinline__ float tf32r(float x) {
    uint32_t u;
    asm("cvt.rna.tf32.f32 %0, %1;" : "=r"(u) : "f"(x));
    return __uint_as_float(u);
}

__device__ __forceinline__ void mma_tf32(float c[4],
                                         uint32_t a0, uint32_t a1, uint32_t a2, uint32_t a3,
                                         uint32_t b0, uint32_t b1) {
    asm volatile(
        "mma.sync.aligned.m16n8k8.row.col.f32.tf32.tf32.f32 "
        "{%0,%1,%2,%3}, {%4,%5,%6,%7}, {%8,%9}, {%0,%1,%2,%3};"
        : "+f"(c[0]), "+f"(c[1]), "+f"(c[2]), "+f"(c[3])
        : "r"(a0), "r"(a1), "r"(a2), "r"(a3), "r"(b0), "r"(b1));
}

__device__ __forceinline__ void cpa16(float* s, const float* g) {
    uint32_t sa = (uint32_t)__cvta_generic_to_shared(s);
    asm volatile("cp.async.cg.shared.global [%0], [%1], 16;" :: "r"(sa), "l"(g));
}
#define CP_COMMIT() asm volatile("cp.async.commit_group;")
#define CP_WAIT0()  asm volatile("cp.async.wait_group 0;")

// ---------------- elementwise tf32 pre-round ----------------
__global__ void __launch_bounds__(256) cvt_tf32(const float* __restrict__ src,
                                                float* __restrict__ dst, int n4) {
    int i = blockIdx.x * 256 + threadIdx.x;
    if (i < n4) {
        float4 t = ((const float4*)src)[i];
        ((float4*)dst)[i] = make_float4(tf32r(t.x), tf32r(t.y), tf32r(t.z), tf32r(t.w));
    }
}

// ---------------- lengths from padding mask (dtype-sniffing) ----------------
__global__ void lengths_kernel(const unsigned char* __restrict__ mask) {
    int tid = threadIdx.x;
    if (tid < B_) g_len[tid] = 0;
    __syncthreads();
    int mode;
    if (mask[1] != 0) mode = 0;                                  // 1-byte bool
    else if (mask[2] == 0x80 && mask[3] == 0x3f) mode = 3;       // float32
    else if (mask[4] != 0) mode = 1;                             // int32
    else mode = 2;                                               // int64
    int c0 = 0, c1 = 0;
    for (int i = tid; i < B_ * S_; i += blockDim.x) {
        bool v;
        switch (mode) {
            case 0:  v = mask[i] != 0; break;
            case 1:  v = ((const int*)mask)[i] != 0; break;
            case 2:  v = ((const long long*)mask)[i] != 0LL; break;
            default: v = ((const float*)mask)[i] != 0.0f; break;
        }
        if (i < S_) c0 += v ? 1 : 0; else c1 += v ? 1 : 0;
    }
    if (c0) atomicAdd(&g_len[0], c0);
    if (c1) atomicAdd(&g_len[1], c1);
}

// ---------------- NT tf32 GEMM, cp.async double-buffered ----------------
// Inputs pre-rounded to tf32 -> no cvt in the inner loop.
#define GEMM_SMEM_FLOATS (4 * 128 * 36)
#define GEMM_SMEM_BYTES  (GEMM_SMEM_FLOATS * 4)

__global__ void __launch_bounds__(256) gemm_tf32(const float* __restrict__ A,
                                                 const float* __restrict__ Bm,
                                                 float* __restrict__ C,
                                                 int M, int N, int K) {
    extern __shared__ float sm[];
    float* As = sm;                    // [2][128][36]
    float* Bs = sm + 2 * 128 * 36;     // [2][128][36]
    const int tid = threadIdx.x, lane = tid & 31, warp = tid >> 5;
    const int wm = warp >> 2, wn = warp & 3;
    const int qr = lane >> 2, qc = lane & 3;
    const int m0 = blockIdx.y * 128, n0 = blockIdx.x * 128;

    float acc[4][4][4];
#pragma unroll
    for (int mi = 0; mi < 4; mi++)
#pragma unroll
        for (int ni = 0; ni < 4; ni++)
#pragma unroll
            for (int e = 0; e < 4; e++) acc[mi][ni][e] = 0.f;

    const int nkt = K >> 5;
#pragma unroll
    for (int i = 0; i < 4; i++) {
        int idx = tid + i * 256;
        int r = idx >> 3, s = (idx & 7) * 4;
        cpa16(As + r * 36 + s, A  + (size_t)(m0 + r) * K + s);
        cpa16(Bs + r * 36 + s, Bm + (size_t)(n0 + r) * K + s);
    }
    CP_COMMIT();

    for (int kt = 0; kt < nkt; kt++) {
        const int buf = kt & 1;
        CP_WAIT0();
        __syncthreads();
        if (kt + 1 < nkt) {
            const int ko = (kt + 1) * 32, nb = buf ^ 1;
#pragma unroll
            for (int i = 0; i < 4; i++) {
                int idx = tid + i * 256;
                int r = idx >> 3, s = (idx & 7) * 4;
                cpa16(As + (nb * 128 + r) * 36 + s, A  + (size_t)(m0 + r) * K + ko + s);
                cpa16(Bs + (nb * 128 + r) * 36 + s, Bm + (size_t)(n0 + r) * K + ko + s);
            }
        }
        CP_COMMIT();
        const float* Ab = As + buf * 128 * 36;
        const float* Bb = Bs + buf * 128 * 36;
#pragma unroll
        for (int ks = 0; ks < 4; ks++) {
            const int k = ks * 8 + qc;
            uint32_t af[4][4];
#pragma unroll
            for (int mi = 0; mi < 4; mi++) {
                const float* ar = Ab + (wm * 64 + mi * 16 + qr) * 36;
                af[mi][0] = __float_as_uint(ar[k]);
                af[mi][1] = __float_as_uint(ar[8 * 36 + k]);
                af[mi][2] = __float_as_uint(ar[k + 4]);
                af[mi][3] = __float_as_uint(ar[8 * 36 + k + 4]);
            }
#pragma unroll
            for (int ni = 0; ni < 4; ni++) {
                const float* br = Bb + (wn * 32 + ni * 8 + qr) * 36;
                uint32_t b0 = __float_as_uint(br[k]);
                uint32_t b1 = __float_as_uint(br[k + 4]);
#pragma unroll
                for (int mi = 0; mi < 4; mi++)
                    mma_tf32(acc[mi][ni], af[mi][0], af[mi][1], af[mi][2], af[mi][3], b0, b1);
            }
        }
    }

#pragma unroll
    for (int mi = 0; mi < 4; mi++) {
        int r = m0 + wm * 64 + mi * 16 + qr;
#pragma unroll
        for (int ni = 0; ni < 4; ni++) {
            int c = n0 + wn * 32 + ni * 8 + qc * 2;
            *(float2*)&C[(size_t)r * N + c]       = make_float2(acc[mi][ni][0], acc[mi][ni][1]);
            *(float2*)&C[(size_t)(r + 8) * N + c] = make_float2(acc[mi][ni][2], acc[mi][ni][3]);
        }
    }
}

// ---------------- RoPE + scatter, writes tf32-rounded q/k/v ----------------
__global__ void __launch_bounds__(256) rope_kernel(const float* __restrict__ sinb,
                                                   const float* __restrict__ cosb) {
    int idx = blockIdx.x * 256 + threadIdx.x;   // over B*S*H*HD = 4194304
    int d = idx & 63;
    int h = (idx >> 6) & 15;
    int s = (idx >> 10) & (S_ - 1);
    int b = idx >> 21;
    size_t base = ((size_t)(b * S_ + s)) * (3 * TD_) + h * HD_;
    float cv = cosb[s * HD_ + d];
    float sv = sinb[s * HD_ + d];
    int   dp  = (d < 32) ? d + 32 : d - 32;
    float sgn = (d < 32) ? -1.f : 1.f;
    float qv  = g_qkv[base + d],          q2 = g_qkv[base + dp];
    float kv  = g_qkv[base + TD_ + d],    k2 = g_qkv[base + TD_ + dp];
    size_t oidx = (((size_t)(b * H_ + h)) * S_ + s) * HD_ + d;
    g_q[oidx] = tf32r(fmaf(qv, cv, sgn * q2 * sv));
    g_k[oidx] = tf32r(fmaf(kv, cv, sgn * k2 * sv));
    g_v[oidx] = tf32r(g_qkv[base + 2 * TD_ + d]);
}

// ---------------- flash attention v3 (tf32 MMA, no in-loop cvt) ----------------
// 8 warps x 16 q-rows each; warp-local softmax; pi-permuted keys so the QK
// C-fragment == PV A-fragment. Full tiles skip masking entirely.
#define AT_QS 0
#define AT_KS (128 * 68)
#define AT_VS (AT_KS + 2 * 128 * 68)
#define ATTN_SMEM_FLOATS (AT_VS + 2 * 128 * 72)
#define ATTN_SMEM_BYTES  (ATTN_SMEM_FLOATS * 4)

__global__ void __launch_bounds__(256, 1) attn_tf32() {
    extern __shared__ float sm[];
    float (*Qs)[68] = (float(*)[68])(sm + AT_QS);
    float* smK = sm + AT_KS;      // [2][128][68]
    float* smV = sm + AT_VS;      // [2][128][72]

    const int qt = (int)gridDim.x - 1 - (int)blockIdx.x;   // heavy CTAs first
    const int bh = blockIdx.y;
    const int b = bh >> 4, h = bh & 15;
    const int len = g_len[b];
    const int qbase = qt * 128;
    const float* qp = g_q + (size_t)bh * S_ * HD_;
    const float* kp = g_k + (size_t)bh * S_ * HD_;
    const float* vp = g_v + (size_t)bh * S_ * HD_;

    const int tid = threadIdx.x, lane = tid & 31, w = tid >> 5;
    const int qr = lane >> 2, qc = lane & 3;
    const int piq = (qr & 1) ? (qr >> 1) + 4 : (qr >> 1);   // pi(qr)

    int nkt = qt + 1;
    int lkt = (len + 127) >> 7;
    if (lkt < nkt) nkt = lkt;

    // prologue: cp.async K/V tile 0 (already tf32-valid bits)
#pragma unroll
    for (int i = 0; i < 8; i++) {
        int idx = tid + i * 256;
        int r = idx >> 4, s = (idx & 15) * 4;
        cpa16(smK + r * 68 + s, kp + (size_t)r * HD_ + s);
        cpa16(smV + r * 72 + s, vp + (size_t)r * HD_ + s);
    }
    CP_COMMIT();

    // Q tile: scale by 1/8 (exact power of 2 -> stays tf32-valid)
    for (int i = tid; i < 2048; i += 256) {
        int r = i >> 4, d4 = (i & 15) << 2;
        float4 t = *(const float4*)&qp[(size_t)(qbase + r) * HD_ + d4];
        *(float4*)&Qs[r][d4] = make_float4(t.x * 0.125f, t.y * 0.125f,
                                           t.z * 0.125f, t.w * 0.125f);
    }

    float m0r = -INFINITY, m1r = -INFINITY, l0 = 0.f, l1 = 0.f;
    float o[8][4];
#pragma unroll
    for (int nd = 0; nd < 8; nd++)
#pragma unroll
        for (int e = 0; e < 4; e++) o[nd][e] = 0.f;

    for (int kt = 0; kt < nkt; kt++) {
        const int buf = kt & 1;
        const int kb = kt * 128;
        CP_WAIT0();
        __syncthreads();
        if (kt + 1 < nkt) {
            const int nb = buf ^ 1, ko = (kt + 1) * 128;
#pragma unroll
            for (int i = 0; i < 8; i++) {
                int idx = tid + i * 256;
                int r = idx >> 4, s = (idx & 15) * 4;
                cpa16(smK + (nb * 128 + r) * 68 + s, kp + (size_t)(ko + r) * HD_ + s);
                cpa16(smV + (nb * 128 + r) * 72 + s, vp + (size_t)(ko + r) * HD_ + s);
            }
        }
        CP_COMMIT();
        const float* Kb = smK + buf * 128 * 68;
        const float* Vb = smV + buf * 128 * 72;

        // ---- QK^T: 16 rows x 128 keys, keys column-permuted by pi ----
        float sf[16][4];
#pragma unroll
        for (int ni = 0; ni < 16; ni++)
#pragma unroll
            for (int e = 0; e < 4; e++) sf[ni][e] = 0.f;

#pragma unroll
        for (int ks = 0; ks < 8; ks++) {
            const int k = ks * 8 + qc;
            const float* ar = Qs[w * 16 + qr];
            uint32_t a0 = __float_as_uint(ar[k]);
            uint32_t a1 = __float_as_uint(ar[8 * 68 + k]);
            uint32_t a2 = __float_as_uint(ar[k + 4]);
            uint32_t a3 = __float_as_uint(ar[8 * 68 + k + 4]);
#pragma unroll
            for (int ni = 0; ni < 16; ni++) {
                const float* kr = Kb + (ni * 8 + piq) * 68;
                uint32_t b0 = __float_as_uint(kr[k]);
                uint32_t b1 = __float_as_uint(kr[k + 4]);
                mma_tf32(sf[ni], a0, a1, a2, a3, b0, b1);
            }
        }

        // ---- row max (masked only on diagonal / len-boundary tiles) ----
        const int rl = qbase + w * 16 + qr, rh = rl + 8;
        float mx0 = -INFINITY, mx1 = -INFINITY;
        if (kt == qt || kb + 128 > len) {
#pragma unroll
            for (int ni = 0; ni < 16; ni++) {
                int k0 = kb + ni * 8 + qc, k1 = k0 + 4;
                if (k0 > rl || k0 >= len) sf[ni][0] = -INFINITY;
                if (k1 > rl || k1 >= len) sf[ni][1] = -INFINITY;
                if (k0 > rh || k0 >= len) sf[ni][2] = -INFINITY;
                if (k1 > rh || k1 >= len) sf[ni][3] = -INFINITY;
                mx0 = fmaxf(mx0, fmaxf(sf[ni][0], sf[ni][1]));
                mx1 = fmaxf(mx1, fmaxf(sf[ni][2], sf[ni][3]));
            }
        } else {
#pragma unroll
            for (int ni = 0; ni < 16; ni++) {
                mx0 = fmaxf(mx0, fmaxf(sf[ni][0], sf[ni][1]));
                mx1 = fmaxf(mx1, fmaxf(sf[ni][2], sf[ni][3]));
            }
        }
        mx0 = fmaxf(mx0, __shfl_xor_sync(0xffffffffu, mx0, 1));
        mx0 = fmaxf(mx0, __shfl_xor_sync(0xffffffffu, mx0, 2));
        mx1 = fmaxf(mx1, __shfl_xor_sync(0xffffffffu, mx1, 1));
        mx1 = fmaxf(mx1, __shfl_xor_sync(0xffffffffu, mx1, 2));

        float mn0 = fmaxf(m0r, mx0), mn1 = fmaxf(m1r, mx1);
        float corr0 = __expf(m0r - mn0), corr1 = __expf(m1r - mn1);
        m0r = mn0; m1r = mn1;

        // ---- exp + row sum; P (tf32-rounded) kept in sf regs ----
        float s0 = 0.f, s1 = 0.f;
#pragma unroll
        for (int ni = 0; ni < 16; ni++) {
            float p0 = __expf(sf[ni][0] - mn0);
            float p1 = __expf(sf[ni][1] - mn0);
            float p2 = __expf(sf[ni][2] - mn1);
            float p3 = __expf(sf[ni][3] - mn1);
            s0 += p0 + p1; s1 += p2 + p3;
            sf[ni][0] = tf32r(p0); sf[ni][1] = tf32r(p1);
            sf[ni][2] = tf32r(p2); sf[ni][3] = tf32r(p3);
        }
        s0 += __shfl_xor_sync(0xffffffffu, s0, 1);
        s0 += __shfl_xor_sync(0xffffffffu, s0, 2);
        s1 += __shfl_xor_sync(0xffffffffu, s1, 1);
        s1 += __shfl_xor_sync(0xffffffffu, s1, 2);
        l0 = l0 * corr0 + s0;
        l1 = l1 * corr1 + s1;
#pragma unroll
        for (int nd = 0; nd < 8; nd++) {
            o[nd][0] *= corr0; o[nd][1] *= corr0;
            o[nd][2] *= corr1; o[nd][3] *= corr1;
        }

        // ---- O += P V: A-fragment straight from score regs (pi trick) ----
#pragma unroll
        for (int ks2 = 0; ks2 < 16; ks2++) {
            uint32_t a0 = __float_as_uint(sf[ks2][0]);   // (row qr,  key qc)
            uint32_t a1 = __float_as_uint(sf[ks2][2]);   // (row qr+8,key qc)
            uint32_t a2 = __float_as_uint(sf[ks2][1]);   // (row qr,  key qc+4)
            uint32_t a3 = __float_as_uint(sf[ks2][3]);   // (row qr+8,key qc+4)
            const float* v0 = Vb + (ks2 * 8 + qc) * 72;
            const float* v1 = v0 + 4 * 72;
#pragma unroll
            for (int nd = 0; nd < 8; nd++) {
                int dcol = nd * 8 + qr;
                uint32_t b0 = __float_as_uint(v0[dcol]);
                uint32_t b1 = __float_as_uint(v1[dcol]);
                mma_tf32(o[nd], a0, a1, a2, a3, b0, b1);
            }
        }
    }

    // ---- normalize + write tf32-rounded (feeds out-proj GEMM) ----
    const float inv0 = 1.f / l0, inv1 = 1.f / l1;
    const int rl = qbase + w * 16 + qr;
#pragma unroll
    for (int nd = 0; nd < 8; nd++) {
        int c = h * HD_ + nd * 8 + qc * 2;
        *(float2*)&g_attn[((size_t)b * S_ + rl) * TD_ + c] =
            make_float2(tf32r(o[nd][0] * inv0), tf32r(o[nd][1] * inv0));
        *(float2*)&g_attn[((size_t)b * S_ + rl + 8) * TD_ + c] =
            make_float2(tf32r(o[nd][2] * inv1), tf32r(o[nd][3] * inv1));
    }
}

// ---------------- launch ----------------
extern "C" void kernel_launch(void* const* d_in, const int* in_sizes, int n_in,
                              void* d_out, int out_size) {
    const float* query = (const float*)d_in[0];
    const float* W_in  = (const float*)d_in[1];
    const float* W_out = (const float*)d_in[2];
    const float* sinb  = (const float*)d_in[3];
    const float* cosb  = (const float*)d_in[4];
    const unsigned char* mask = (const unsigned char*)d_in[5];
    float* out = (float*)d_out;

    void *p_qkv = nullptr, *p_attn = nullptr, *p_qt = nullptr, *p_wi = nullptr, *p_wo = nullptr;
    cudaGetSymbolAddress(&p_qkv, g_qkv);
    cudaGetSymbolAddress(&p_attn, g_attn);
    cudaGetSymbolAddress(&p_qt, g_qt);
    cudaGetSymbolAddress(&p_wi, g_wi);
    cudaGetSymbolAddress(&p_wo, g_wo);
    cudaFuncSetAttribute(attn_tf32, cudaFuncAttributeMaxDynamicSharedMemorySize,
                         ATTN_SMEM_BYTES);
    cudaFuncSetAttribute(gemm_tf32, cudaFuncAttributeMaxDynamicSharedMemorySize,
                         GEMM_SMEM_BYTES);

    lengths_kernel<<<1, 256>>>(mask);

    // pre-round GEMM inputs to tf32 (once; removes all in-loop cvt)
    cvt_tf32<<<(B_ * S_ * DM_ / 4 + 255) / 256, 256>>>(query, (float*)p_qt, B_ * S_ * DM_ / 4);
    cvt_tf32<<<(3 * TD_ * DM_ / 4 + 255) / 256, 256>>>(W_in, (float*)p_wi, 3 * TD_ * DM_ / 4);
    cvt_tf32<<<(DM_ * TD_ / 4 + 255) / 256, 256>>>(W_out, (float*)p_wo, DM_ * TD_ / 4);

    // QKV projection: [4096,1024] x [3072,1024]^T -> [4096,3072]
    gemm_tf32<<<dim3(3 * TD_ / 128, B_ * S_ / 128), 256, GEMM_SMEM_BYTES>>>(
        (const float*)p_qt, (const float*)p_wi, (float*)p_qkv, B_ * S_, 3 * TD_, DM_);

    // RoPE + scatter to [B,H,S,HD] (tf32-rounded)
    rope_kernel<<<(B_ * S_ * H_ * HD_) / 256, 256>>>(sinb, cosb);

    // causal flash attention (tf32 tensor-core)
    attn_tf32<<<dim3(S_ / 128, B_ * H_), 256, ATTN_SMEM_BYTES>>>();

    // output projection: [4096,1024] x [1024,1024]^T -> d_out
    gemm_tf32<<<dim3(DM_ / 128, B_ * S_ / 128), 256, GEMM_SMEM_BYTES>>>(
        (const float*)p_attn, (const float*)p_wo, out, B_ * S_, DM_, TD_);
}